// round 1
// baseline (speedup 1.0000x reference)
#include <cuda_runtime.h>
#include <math.h>

#define D 1024
#define S 128
#define DECAY 0.99f
#define INHIB 1.5f
#define TOPK 51
#define SCAN_R 4

// Scratch (static device globals — no allocation).
__device__ float g_sbuf[S * D];   // sparsified token vectors, dense [S][D]
__device__ float g_gbuf[S];       // per-step gain (1 - c*INHIB)

// ---------------------------------------------------------------------------
// Kernel 1: sparsify each token. One block per token t (256 threads, 4 vals each).
// Exact k-th-largest threshold via bitwise radix select on nonneg float bits.
// ---------------------------------------------------------------------------
__global__ void __launch_bounds__(256) sparsify_kernel(
    const float* __restrict__ emb, const float* __restrict__ con) {
    const int t = blockIdx.x;
    const int tid = threadIdx.x;
    const int lane = tid & 31, wid = tid >> 5;

    float4 x = reinterpret_cast<const float4*>(emb + (size_t)t * D)[tid];
    float p[4];
    p[0] = fmaxf(x.x, 0.f); p[1] = fmaxf(x.y, 0.f);
    p[2] = fmaxf(x.z, 0.f); p[3] = fmaxf(x.w, 0.f);
    unsigned pb[4];
#pragma unroll
    for (int k = 0; k < 4; ++k) pb[k] = __float_as_uint(p[k]);

    __shared__ unsigned wsum[8];
    __shared__ unsigned cnt_sh;

    // Find max uint T such that count(bits >= T) >= TOPK  ==>  T = bits of
    // the TOPK-th largest value (exact, since nonneg-float order == uint order).
    unsigned thr = 0u;
    for (int b = 30; b >= 0; --b) {
        unsigned cand = thr | (1u << b);
        unsigned c = 0;
#pragma unroll
        for (int k = 0; k < 4; ++k) c += (pb[k] >= cand) ? 1u : 0u;
#pragma unroll
        for (int o = 16; o > 0; o >>= 1) c += __shfl_xor_sync(0xffffffffu, c, o);
        if (lane == 0) wsum[wid] = c;
        __syncthreads();
        if (tid == 0) {
            unsigned tot = 0;
            for (int w = 0; w < 8; ++w) tot += wsum[w];
            cnt_sh = tot;
        }
        __syncthreads();
        if (cnt_sh >= TOPK) thr = cand;
        __syncthreads();
    }
    float thrf = __uint_as_float(thr);

    float4 sv;
    sv.x = (p[0] >= thrf) ? p[0] : 0.f;
    sv.y = (p[1] >= thrf) ? p[1] : 0.f;
    sv.z = (p[2] >= thrf) ? p[2] : 0.f;
    sv.w = (p[3] >= thrf) ? p[3] : 0.f;
    reinterpret_cast<float4*>(g_sbuf + (size_t)t * D)[tid] = sv;

    if (tid == 0) g_gbuf[t] = 1.0f - con[t] * INHIB;
}

// ---------------------------------------------------------------------------
// Kernel 2: the scan. Each (i,j) entry of the state evolves independently:
//     v <- relu(DECAY*v + s_t[i]*s_t[j]*g_t)
// Thread owns SCAN_R rows x 4 cols (float4), keeps v in registers across all
// 128 steps, and streams every snapshot straight to its output slice.
// Grid: D/SCAN_R = 256 blocks x 256 threads (threads cover all 1024 cols).
// ---------------------------------------------------------------------------
__global__ void __launch_bounds__(256) scan_kernel(float* __restrict__ states) {
    const int tid = threadIdx.x;
    const int i0 = blockIdx.x * SCAN_R;
    const int j = tid * 4;

    __shared__ float si_sh[S * SCAN_R];  // s_t[i0+r] for all t
    __shared__ float g_sh[S];
    for (int idx = tid; idx < S * SCAN_R; idx += 256) {
        int tt = idx >> 2, r = idx & 3;
        si_sh[idx] = g_sbuf[(size_t)tt * D + i0 + r];
    }
    if (tid < S) g_sh[tid] = g_gbuf[tid];
    __syncthreads();

    float4 v[SCAN_R];
#pragma unroll
    for (int r = 0; r < SCAN_R; ++r) v[r] = make_float4(0.f, 0.f, 0.f, 0.f);

    // Prefetch s_t[j..j+3] one step ahead.
    float4 sj = __ldg(reinterpret_cast<const float4*>(g_sbuf + j));
    for (int t = 0; t < S; ++t) {
        float4 sjn = sj;
        if (t + 1 < S)
            sjn = __ldg(reinterpret_cast<const float4*>(g_sbuf + (size_t)(t + 1) * D + j));
        const float g = g_sh[t];
        float* o = states + (size_t)t * D * D + j;
#pragma unroll
        for (int r = 0; r < SCAN_R; ++r) {
            const float a = si_sh[t * SCAN_R + r] * g;
            v[r].x = fmaxf(fmaf(a, sj.x, DECAY * v[r].x), 0.f);
            v[r].y = fmaxf(fmaf(a, sj.y, DECAY * v[r].y), 0.f);
            v[r].z = fmaxf(fmaf(a, sj.z, DECAY * v[r].z), 0.f);
            v[r].w = fmaxf(fmaf(a, sj.w, DECAY * v[r].w), 0.f);
            __stcs(reinterpret_cast<float4*>(o + (size_t)(i0 + r) * D), v[r]);
        }
        sj = sjn;
    }
}

// ---------------------------------------------------------------------------
// Kernel 3: drift. One block per step t. expectation[j] = sum_i s[i]*state[t-1][i,j]
// — only nonzero rows of s contribute (~51 of 1024). Fixed ascending-i order
// for determinism. state[-1] = 0 => drift_0 = ||s_0||.
// ---------------------------------------------------------------------------
__global__ void __launch_bounds__(256) drift_kernel(
    const float* __restrict__ states, float* __restrict__ drifts) {
    const int t = blockIdx.x;
    const int tid = threadIdx.x;
    const int lane = tid & 31, wid = tid >> 5;
    const int j = tid * 4;

    __shared__ float ssh[D];
    reinterpret_cast<float4*>(ssh)[tid] =
        reinterpret_cast<const float4*>(g_sbuf + (size_t)t * D)[tid];
    __syncthreads();

    float4 e = make_float4(0.f, 0.f, 0.f, 0.f);
    if (t > 0) {
        const float* st = states + (size_t)(t - 1) * D * D;
        for (int i = 0; i < D; ++i) {
            const float si = ssh[i];          // uniform across block
            if (si != 0.f) {                   // warp-uniform branch
                float4 r4 = __ldg(reinterpret_cast<const float4*>(st + (size_t)i * D + j));
                e.x = fmaf(si, r4.x, e.x);
                e.y = fmaf(si, r4.y, e.y);
                e.z = fmaf(si, r4.z, e.z);
                e.w = fmaf(si, r4.w, e.w);
            }
        }
    }

    const float dx = ssh[j + 0] - e.x;
    const float dy = ssh[j + 1] - e.y;
    const float dz = ssh[j + 2] - e.z;
    const float dw = ssh[j + 3] - e.w;
    float sum = dx * dx + dy * dy + dz * dz + dw * dw;
#pragma unroll
    for (int o = 16; o > 0; o >>= 1) sum += __shfl_xor_sync(0xffffffffu, sum, o);

    __shared__ float ws[8];
    if (lane == 0) ws[wid] = sum;
    __syncthreads();
    if (tid == 0) {
        float tot = 0.f;
        for (int w = 0; w < 8; ++w) tot += ws[w];
        drifts[t] = sqrtf(tot);
    }
}

// ---------------------------------------------------------------------------
extern "C" void kernel_launch(void* const* d_in, const int* in_sizes, int n_in,
                              void* d_out, int out_size) {
    // Defensive input identification by size.
    const float* emb;
    const float* con;
    if (in_sizes[0] == S) {
        con = (const float*)d_in[0];
        emb = (const float*)d_in[1];
    } else {
        emb = (const float*)d_in[0];
        con = (const float*)d_in[1];
    }
    float* out = (float*)d_out;
    float* drifts = out;        // [S]
    float* states = out + S;    // [S, D, D]

    sparsify_kernel<<<S, 256>>>(emb, con);
    scan_kernel<<<D / SCAN_R, 256>>>(states);
    drift_kernel<<<S, 256>>>(states, drifts);
}

// round 2
// speedup vs baseline: 1.2317x; 1.2317x over previous
#include <cuda_runtime.h>
#include <math.h>

#define D 1024
#define S 128
#define DECAY 0.99f
#define INHIB 1.5f
#define TOPK 51
#define SCAN_R 4

// Scratch (static device globals — no allocation).
__device__ float g_sbuf[S * D];    // sparsified token vectors, dense [S][D]
__device__ float g_expect[S * D];  // expectation_t[j] = s_t @ state_{t-1}, accumulated by scan

// ---------------------------------------------------------------------------
// Kernel 1: sparsify. grid=S blocks, block=64 threads.
//   warp 0: exact radix top-k select for token t (32 values/lane, no barriers)
//   warp 1: zero g_expect row t
// Exactness: nonneg-float order == uint order, so the greedy bit construction
// finds the exact bits of the TOPK-th largest relu value.
// ---------------------------------------------------------------------------
__global__ void __launch_bounds__(64) sparsify_kernel(const float* __restrict__ emb) {
    const int t = blockIdx.x;
    const int wid = threadIdx.x >> 5;
    const int lane = threadIdx.x & 31;

    if (wid == 1) {  // zero g_expect[t*D .. t*D+D)
        float4 z = make_float4(0.f, 0.f, 0.f, 0.f);
        float4* e4 = reinterpret_cast<float4*>(g_expect + (size_t)t * D);
#pragma unroll
        for (int c = 0; c < 8; ++c) e4[c * 32 + lane] = z;
        return;
    }

    // warp 0: load 1024 floats, 32 per lane (coalesced float4 chunks)
    float p[32];
    const float4* row = reinterpret_cast<const float4*>(emb + (size_t)t * D);
#pragma unroll
    for (int c = 0; c < 8; ++c) {
        float4 x = row[c * 32 + lane];
        p[c * 4 + 0] = fmaxf(x.x, 0.f);
        p[c * 4 + 1] = fmaxf(x.y, 0.f);
        p[c * 4 + 2] = fmaxf(x.z, 0.f);
        p[c * 4 + 3] = fmaxf(x.w, 0.f);
    }
    unsigned pb[32];
#pragma unroll
    for (int k = 0; k < 32; ++k) pb[k] = __float_as_uint(p[k]);

    // Max uint T with count(bits >= T) >= TOPK  ==  bits of k-th largest value.
    unsigned thr = 0u;
    for (int b = 30; b >= 0; --b) {
        unsigned cand = thr | (1u << b);
        int c = 0;
#pragma unroll
        for (int k = 0; k < 32; ++k) c += (pb[k] >= cand) ? 1 : 0;
        c = __reduce_add_sync(0xffffffffu, c);  // uniform result on all lanes
        if (c >= TOPK) thr = cand;
    }

    float4* out = reinterpret_cast<float4*>(g_sbuf + (size_t)t * D);
#pragma unroll
    for (int c = 0; c < 8; ++c) {
        float4 sv;
        sv.x = (pb[c * 4 + 0] >= thr) ? p[c * 4 + 0] : 0.f;
        sv.y = (pb[c * 4 + 1] >= thr) ? p[c * 4 + 1] : 0.f;
        sv.z = (pb[c * 4 + 2] >= thr) ? p[c * 4 + 2] : 0.f;
        sv.w = (pb[c * 4 + 3] >= thr) ? p[c * 4 + 3] : 0.f;
        out[c * 32 + lane] = sv;
    }
}

// ---------------------------------------------------------------------------
// Kernel 2: the scan, with fused expectation accumulation.
// Each (i,j) state entry evolves independently:
//     v <- relu(DECAY*v + s_t[i]*s_t[j]*g_t),   g_t = 1 - c_t*INHIB
// Thread owns SCAN_R=4 rows x 4 cols; v stays in registers across all 128
// steps; every snapshot streams straight to its output slice. After producing
// state_t, the block contributes s_{t+1}[i]*v[i,j] to g_expect[t+1] via
// atomics (block-uniform skip when the 4 s-values are all zero, ~81% of steps).
// Grid: D/SCAN_R = 256 blocks x 256 threads.
// ---------------------------------------------------------------------------
__global__ void __launch_bounds__(256) scan_kernel(const float* __restrict__ con,
                                                  float* __restrict__ states) {
    const int tid = threadIdx.x;
    const int i0 = blockIdx.x * SCAN_R;
    const int j = tid * 4;

    __shared__ float4 si_sh[S];  // s_t[i0..i0+3] for all t
    __shared__ float g_sh[S];
    if (tid < S) {
        si_sh[tid] = *reinterpret_cast<const float4*>(g_sbuf + (size_t)tid * D + i0);
        g_sh[tid] = 1.0f - con[tid] * INHIB;
    }
    __syncthreads();

    float4 v[SCAN_R];
#pragma unroll
    for (int r = 0; r < SCAN_R; ++r) v[r] = make_float4(0.f, 0.f, 0.f, 0.f);

    float4 sj = __ldg(reinterpret_cast<const float4*>(g_sbuf + j));  // s_t[j..j+3]
    for (int t = 0; t < S; ++t) {
        float4 sjn = sj;
        if (t + 1 < S)
            sjn = __ldg(reinterpret_cast<const float4*>(g_sbuf + (size_t)(t + 1) * D + j));
        const float g = g_sh[t];
        const float4 si = si_sh[t];
        const float a0 = si.x * g, a1 = si.y * g, a2 = si.z * g, a3 = si.w * g;
        float* o = states + (size_t)t * D * D + j;

        v[0].x = fmaxf(fmaf(a0, sj.x, DECAY * v[0].x), 0.f);
        v[0].y = fmaxf(fmaf(a0, sj.y, DECAY * v[0].y), 0.f);
        v[0].z = fmaxf(fmaf(a0, sj.z, DECAY * v[0].z), 0.f);
        v[0].w = fmaxf(fmaf(a0, sj.w, DECAY * v[0].w), 0.f);
        v[1].x = fmaxf(fmaf(a1, sj.x, DECAY * v[1].x), 0.f);
        v[1].y = fmaxf(fmaf(a1, sj.y, DECAY * v[1].y), 0.f);
        v[1].z = fmaxf(fmaf(a1, sj.z, DECAY * v[1].z), 0.f);
        v[1].w = fmaxf(fmaf(a1, sj.w, DECAY * v[1].w), 0.f);
        v[2].x = fmaxf(fmaf(a2, sj.x, DECAY * v[2].x), 0.f);
        v[2].y = fmaxf(fmaf(a2, sj.y, DECAY * v[2].y), 0.f);
        v[2].z = fmaxf(fmaf(a2, sj.z, DECAY * v[2].z), 0.f);
        v[2].w = fmaxf(fmaf(a2, sj.w, DECAY * v[2].w), 0.f);
        v[3].x = fmaxf(fmaf(a3, sj.x, DECAY * v[3].x), 0.f);
        v[3].y = fmaxf(fmaf(a3, sj.y, DECAY * v[3].y), 0.f);
        v[3].z = fmaxf(fmaf(a3, sj.z, DECAY * v[3].z), 0.f);
        v[3].w = fmaxf(fmaf(a3, sj.w, DECAY * v[3].w), 0.f);

        __stcs(reinterpret_cast<float4*>(o + (size_t)(i0 + 0) * D), v[0]);
        __stcs(reinterpret_cast<float4*>(o + (size_t)(i0 + 1) * D), v[1]);
        __stcs(reinterpret_cast<float4*>(o + (size_t)(i0 + 2) * D), v[2]);
        __stcs(reinterpret_cast<float4*>(o + (size_t)(i0 + 3) * D), v[3]);

        // Fused expectation: contribute s_{t+1}[i0+r] * v[r][.] to expect[t+1].
        if (t + 1 < S) {
            const float4 sn = si_sh[t + 1];  // block-uniform
            if (sn.x != 0.f || sn.y != 0.f || sn.z != 0.f || sn.w != 0.f) {
                float4 cacc;
                cacc.x = sn.x * v[0].x + sn.y * v[1].x + sn.z * v[2].x + sn.w * v[3].x;
                cacc.y = sn.x * v[0].y + sn.y * v[1].y + sn.z * v[2].y + sn.w * v[3].y;
                cacc.z = sn.x * v[0].z + sn.y * v[1].z + sn.z * v[2].z + sn.w * v[3].z;
                cacc.w = sn.x * v[0].w + sn.y * v[1].w + sn.z * v[2].w + sn.w * v[3].w;
                float* e = g_expect + (size_t)(t + 1) * D + j;
                atomicAdd(e + 0, cacc.x);
                atomicAdd(e + 1, cacc.y);
                atomicAdd(e + 2, cacc.z);
                atomicAdd(e + 3, cacc.w);
            }
        }
        sj = sjn;
    }
}

// ---------------------------------------------------------------------------
// Kernel 3: finalize drifts from accumulated expectations.
// drift_t = || s_t - expect_t ||   (expect_0 stays zero => drift_0 = ||s_0||)
// ---------------------------------------------------------------------------
__global__ void __launch_bounds__(256) finalize_kernel(float* __restrict__ drifts) {
    const int t = blockIdx.x;
    const int tid = threadIdx.x;
    const int lane = tid & 31, wid = tid >> 5;

    float4 s4 = reinterpret_cast<const float4*>(g_sbuf + (size_t)t * D)[tid];
    float4 e4 = reinterpret_cast<const float4*>(g_expect + (size_t)t * D)[tid];
    const float dx = s4.x - e4.x, dy = s4.y - e4.y;
    const float dz = s4.z - e4.z, dw = s4.w - e4.w;
    float sum = dx * dx + dy * dy + dz * dz + dw * dw;
#pragma unroll
    for (int o = 16; o > 0; o >>= 1) sum += __shfl_xor_sync(0xffffffffu, sum, o);

    __shared__ float ws[8];
    if (lane == 0) ws[wid] = sum;
    __syncthreads();
    if (tid == 0) {
        float tot = 0.f;
        for (int w = 0; w < 8; ++w) tot += ws[w];
        drifts[t] = sqrtf(tot);
    }
}

// ---------------------------------------------------------------------------
extern "C" void kernel_launch(void* const* d_in, const int* in_sizes, int n_in,
                              void* d_out, int out_size) {
    const float* emb;
    const float* con;
    if (in_sizes[0] == S) {
        con = (const float*)d_in[0];
        emb = (const float*)d_in[1];
    } else {
        emb = (const float*)d_in[0];
        con = (const float*)d_in[1];
    }
    float* out = (float*)d_out;
    float* drifts = out;      // [S]
    float* states = out + S;  // [S, D, D]

    sparsify_kernel<<<S, 64>>>(emb);
    scan_kernel<<<D / SCAN_R, 256>>>(con, states);
    finalize_kernel<<<S, 256>>>(drifts);
}